// round 9
// baseline (speedup 1.0000x reference)
#include <cuda_runtime.h>
#include <cuda_bf16.h>
#include <cstdint>

// HashGridEncoding R9: level-major warps, 64 points/block (2 per lane, ILP x2),
// __ldcs streaming hint on level-8 loads only (protect l7 L2 residency).
// Block = 288 threads = 9 warps; warp w = level w.

#define NUM_LEVELS 9

__device__ __forceinline__ void load_pair(const float4* __restrict__ t4, int b,
                                          bool stream, float2& q0, float2& q1)
{
    int a = b >> 1;
    float4 qa = stream ? __ldcs(t4 + a) : __ldg(t4 + a);
    if (b & 1) {
        float4 qb = stream ? __ldcs(t4 + a + 1) : __ldg(t4 + a + 1);
        q0 = make_float2(qa.z, qa.w);
        q1 = make_float2(qb.x, qb.y);
    } else {
        q0 = make_float2(qa.x, qa.y);
        q1 = make_float2(qa.z, qa.w);
    }
}

__device__ __forceinline__ float2 interp_one(
    const float4* __restrict__ tab4,
    float px, float py, float pz, int vi, float vf, bool stream)
{
    float gx = (px + 1.0f) * 0.5f * vf;
    float gy = (py + 1.0f) * 0.5f * vf;
    float gz = (pz + 1.0f) * 0.5f * vf;

    float bxf = floorf(gx);
    float byf = floorf(gy);
    float bzf = floorf(gz);

    float fx = gx - bxf;
    float fy = gy - byf;
    float fz = gz - bzf;

    int ix = (int)bxf;
    int iy = (int)byf;
    int iz = (int)bzf;

    int flat = ix + iy * vi + iz * vi * vi;
    int dz   = vi * vi;

    float2 q000, q100, q010, q110, q001, q101, q011, q111;
    load_pair(tab4, flat,           stream, q000, q100);
    load_pair(tab4, flat + vi,      stream, q010, q110);
    load_pair(tab4, flat + dz,      stream, q001, q101);
    load_pair(tab4, flat + dz + vi, stream, q011, q111);

    float wx0 = 1.0f - fx, wx1 = fx;
    float wy0 = 1.0f - fy, wy1 = fy;
    float wz0 = 1.0f - fz, wz1 = fz;

    float a0x = wx0 * q000.x + wx1 * q100.x;
    float a0y = wx0 * q000.y + wx1 * q100.y;
    float a1x = wx0 * q010.x + wx1 * q110.x;
    float a1y = wx0 * q010.y + wx1 * q110.y;
    float a2x = wx0 * q001.x + wx1 * q101.x;
    float a2y = wx0 * q001.y + wx1 * q101.y;
    float a3x = wx0 * q011.x + wx1 * q111.x;
    float a3y = wx0 * q011.y + wx1 * q111.y;

    float b0x = wy0 * a0x + wy1 * a1x;
    float b0y = wy0 * a0y + wy1 * a1y;
    float b1x = wy0 * a2x + wy1 * a3x;
    float b1y = wy0 * a2y + wy1 * a3y;

    return make_float2(wz0 * b0x + wz1 * b1x,
                       wz0 * b0y + wz1 * b1y);
}

__global__ void __launch_bounds__(288) hashgrid_kernel(
    const float* __restrict__ x,
    const float* __restrict__ table,
    float* __restrict__ out,
    int P)
{
    __shared__ float  sx[192];                  // 64 points x 3 coords
    __shared__ float2 sres[64][NUM_LEVELS];

    int pbase = blockIdx.x * 64;
    int t = threadIdx.x;

    // stage 64 points' coords (192 floats) coalesced
    if (t < 192) {
        int g = pbase * 3 + t;
        sx[t] = (g < P * 3) ? x[g] : 0.0f;
    }
    __syncthreads();

    int w    = t >> 5;          // warp id == level (0..8)
    int lane = t & 31;

    {
        int   vi = 1 << w;
        float vf = (float)vi;
        bool  stream = (w == 8);
        const float4* __restrict__ tab4 = (const float4*)table;

        int l0 = lane;          // point lane
        int l1 = lane + 32;     // point lane+32

        // two independent interpolations -> 8 scattered loads in flight
        float2 r0 = interp_one(tab4, sx[l0 * 3 + 0], sx[l0 * 3 + 1],
                               sx[l0 * 3 + 2], vi, vf, stream);
        float2 r1 = interp_one(tab4, sx[l1 * 3 + 0], sx[l1 * 3 + 1],
                               sx[l1 * 3 + 2], vi, vf, stream);

        sres[l0][w] = r0;
        sres[l1][w] = r1;
    }
    __syncthreads();

    // write-out: 576 float2 by 288 threads, 2 each; thread t covers
    // elements t and t+288 of the block's 64*9 float2 output (contiguous 4.6KB)
    const float2* s2 = &sres[0][0];
    float2* __restrict__ o2 = (float2*)out;
    int base = pbase * NUM_LEVELS;
    int limit = P * NUM_LEVELS;

    int e0 = base + t;
    if (e0 < limit) o2[e0] = s2[t];
    int e1 = base + t + 288;
    if (e1 < limit) o2[e1] = s2[t + 288];
}

extern "C" void kernel_launch(void* const* d_in, const int* in_sizes, int n_in,
                              void* d_out, int out_size)
{
    const float* x     = (const float*)d_in[0];
    const float* table = (const float*)d_in[1];
    float* out         = (float*)d_out;

    int P = in_sizes[0] / 3;
    int blocks = (P + 63) / 64;        // 64 points per block, 9 warps
    hashgrid_kernel<<<blocks, 288>>>(x, table, out, P);
}